// round 2
// baseline (speedup 1.0000x reference)
#include <cuda_runtime.h>
#include <math.h>
#include <math_constants.h>

// Problem constants
#define NQc   4096
#define NKc   8192
#define DIN   256
#define DA    64
#define Hc    4
#define DOUTc 256
#define SSPLIT 8
#define KCHUNK (NKc / SSPLIT)   // 1024 keys per split
#define TK     8                // keys per smem tile
#define SCALE  0.125f           // 1/sqrt(64)
#define NEGINF (-CUDART_INF_F)

// ---------------- scratch (static device allocations; no cudaMalloc) ----------------
__device__ float d_Qp[(size_t)Hc * NQc * DA];              // 4 MB
__device__ float d_Kp[(size_t)Hc * NKc * DA];              // 8 MB
__device__ float d_Vp[(size_t)Hc * NKc * DA];              // 8 MB
__device__ float d_gate[(size_t)Hc * NQc];                 // 64 KB
__device__ float d_Pacc[(size_t)Hc * SSPLIT * NQc * DA];   // 32 MB
__device__ float d_Pm[(size_t)Hc * SSPLIT * NQc];
__device__ float d_Pl[(size_t)Hc * SSPLIT * NQc];
__device__ float d_comb[(size_t)NQc * DA];                 // 1 MB

// ---------------- per-head projection: out[h][n][a] = sum_k x[n][k] * W[h][k][a] ----
// Din=256, A=64. Block: 256 thr computes a 32(n) x 64(a) tile for head blockIdx.y.
__global__ void proj_kernel(const float* __restrict__ x, const float* __restrict__ W,
                            int which, int N) {
    float* outp = (which == 0) ? d_Qp : (which == 1) ? d_Kp : d_Vp;
    const int n0 = blockIdx.x * 32;
    const int h  = blockIdx.y;
    __shared__ float xs[32][64];
    __shared__ float ws[64][64];
    const int t  = threadIdx.x;       // 0..255
    const int tx = t & 63;            // a
    const int tz = t >> 6;            // 0..3 (row group)

    float acc[8];
#pragma unroll
    for (int i = 0; i < 8; i++) acc[i] = 0.f;

    for (int k0 = 0; k0 < DIN; k0 += 64) {
        // xs: 32x64 = 512 float4 -> 2 per thread
#pragma unroll
        for (int j = 0; j < 2; j++) {
            int idx = t + 256 * j;
            int r = idx >> 4, c = idx & 15;
            ((float4*)&xs[r][0])[c] =
                ((const float4*)&x[(size_t)(n0 + r) * DIN + k0])[c];
        }
        // ws: 64x64 = 1024 float4 -> 4 per thread
#pragma unroll
        for (int j = 0; j < 4; j++) {
            int idx = t + 256 * j;
            int r = idx >> 4, c = idx & 15;
            ((float4*)&ws[r][0])[c] =
                ((const float4*)&W[((size_t)h * DIN + k0 + r) * DA])[c];
        }
        __syncthreads();
#pragma unroll
        for (int kk = 0; kk < 64; kk++) {
            float w = ws[kk][tx];
#pragma unroll
            for (int i = 0; i < 8; i++) acc[i] += xs[tz + 4 * i][kk] * w;
        }
        __syncthreads();
    }
#pragma unroll
    for (int i = 0; i < 8; i++)
        outp[((size_t)h * N + n0 + tz + 4 * i) * DA + tx] = acc[i];
}

// ---------------- gates: sigmoid(x_Q[n] . Wg[h] + bg[h]), one warp per (h,n) --------
__global__ void gate_kernel(const float* __restrict__ xQ, const float* __restrict__ Wg,
                            const float* __restrict__ bg) {
    int gid  = blockIdx.x * blockDim.x + threadIdx.x;
    int w    = gid >> 5;
    int lane = gid & 31;
    if (w >= Hc * NQc) return;
    int h = w >> 12;           // / 4096
    int n = w & (NQc - 1);
    const float4* xp = (const float4*)(xQ + (size_t)n * DIN);
    const float4* wp = (const float4*)(Wg + (size_t)h * DIN);
    float acc = 0.f;
#pragma unroll
    for (int i = 0; i < 2; i++) {
        float4 xa = xp[lane + 32 * i], wa = wp[lane + 32 * i];
        acc += xa.x * wa.x + xa.y * wa.y + xa.z * wa.z + xa.w * wa.w;
    }
#pragma unroll
    for (int off = 16; off; off >>= 1) acc += __shfl_xor_sync(0xffffffffu, acc, off);
    if (lane == 0) d_gate[w] = 1.f / (1.f + __expf(-(acc + bg[h])));
}

// ---------------- split-K flash attention -------------------------------------------
// grid (128 q-tiles, 8 k-splits); block 128 thr; warp = head, lane = query.
__global__ __launch_bounds__(128, 3)
void attn_kernel(const int* __restrict__ mask) {
    const int qt   = blockIdx.x;
    const int sp   = blockIdx.y;
    const int t    = threadIdx.x;
    const int h    = t >> 5;
    const int lane = t & 31;
    const int q    = qt * 32 + lane;

    __shared__ float Ks[Hc][TK][DA];   // 8 KB
    __shared__ float Vs[Hc][TK][DA];   // 8 KB
    __shared__ int   Ms[32][TK];       // 1 KB

    float4 Qr[16];
    {
        const float4* qp = (const float4*)&d_Qp[((size_t)h * NQc + q) * DA];
#pragma unroll
        for (int i = 0; i < 16; i++) Qr[i] = qp[i];
    }
    float4 acc[16];
#pragma unroll
    for (int i = 0; i < 16; i++) acc[i] = make_float4(0.f, 0.f, 0.f, 0.f);
    float mrun = NEGINF, lrun = 0.f;

    const int kbase = sp * KCHUNK;
    for (int tile = 0; tile < KCHUNK / TK; tile++) {
        const int k0 = kbase + tile * TK;
        // K,V tiles: 4h x 8k x 64d = 512 float4 each -> 4 per thread
#pragma unroll
        for (int j = 0; j < 4; j++) {
            int idx = t + 128 * j;
            int rowIdx = idx >> 4;        // 0..31
            int c  = idx & 15;
            int hh = rowIdx >> 3;
            int kk = rowIdx & 7;
            ((float4*)&Ks[hh][kk][0])[c] =
                ((const float4*)&d_Kp[((size_t)hh * NKc + k0 + kk) * DA])[c];
            ((float4*)&Vs[hh][kk][0])[c] =
                ((const float4*)&d_Vp[((size_t)hh * NKc + k0 + kk) * DA])[c];
        }
        // mask tile: 32q x 8k ints = 64 int4
        if (t < 64) {
            int row = t >> 1, c = t & 1;
            ((int4*)&Ms[row][0])[c] =
                ((const int4*)(mask + (size_t)(qt * 32 + row) * NKc + k0))[c];
        }
        __syncthreads();

        float s[TK];
        float tmax = NEGINF;
#pragma unroll
        for (int k = 0; k < TK; k++) {
            const float4* kp = (const float4*)&Ks[h][k][0];
            float4 sv = make_float4(0.f, 0.f, 0.f, 0.f);
#pragma unroll
            for (int i = 0; i < 16; i++) {
                float4 kv = kp[i];
                float4 qv = Qr[i];
                sv.x += qv.x * kv.x; sv.y += qv.y * kv.y;
                sv.z += qv.z * kv.z; sv.w += qv.w * kv.w;
            }
            float v = (sv.x + sv.y) + (sv.z + sv.w);
            v *= SCALE;
            if (Ms[lane][k] == 0) v = NEGINF;
            s[k] = v;
            tmax = fmaxf(tmax, v);
        }
        float mnew = fmaxf(mrun, tmax);
        if (mnew > NEGINF) {            // skip if everything so far masked (avoids inf-inf NaN)
            float corr = __expf(mrun - mnew);   // mrun=-inf -> corr=0 (correct)
            lrun *= corr;
#pragma unroll
            for (int i = 0; i < 16; i++) {
                acc[i].x *= corr; acc[i].y *= corr;
                acc[i].z *= corr; acc[i].w *= corr;
            }
#pragma unroll
            for (int k = 0; k < TK; k++) {
                float p = __expf(s[k] - mnew);  // s=-inf -> 0
                lrun += p;
                const float4* vp = (const float4*)&Vs[h][k][0];
#pragma unroll
                for (int i = 0; i < 16; i++) {
                    float4 vv = vp[i];
                    acc[i].x += p * vv.x; acc[i].y += p * vv.y;
                    acc[i].z += p * vv.z; acc[i].w += p * vv.w;
                }
            }
            mrun = mnew;
        }
        __syncthreads();
    }

    const size_t base = (((size_t)h * SSPLIT + sp) * NQc + q);
    d_Pm[base] = mrun;
    d_Pl[base] = lrun;
    float4* pout = (float4*)&d_Pacc[base * DA];
#pragma unroll
    for (int i = 0; i < 16; i++) pout[i] = acc[i];
}

// ---------------- merge splits + softmax finalize + gate combine --------------------
// grid NQ blocks, 64 threads (a-dim)
__global__ void combine_kernel() {
    const int n = blockIdx.x;
    const int a = threadIdx.x;
    float res = 0.f;
#pragma unroll
    for (int h = 0; h < Hc; h++) {
        float mv[SSPLIT];
        float M = NEGINF;
#pragma unroll
        for (int s = 0; s < SSPLIT; s++) {
            mv[s] = d_Pm[((size_t)h * SSPLIT + s) * NQc + n];
            M = fmaxf(M, mv[s]);
        }
        if (!(M > NEGINF)) continue;    // fully masked row (practically impossible)
        float L = 0.f, val = 0.f;
#pragma unroll
        for (int s = 0; s < SSPLIT; s++) {
            float w = __expf(mv[s] - M);            // -inf split -> w=0
            size_t base = ((size_t)h * SSPLIT + s) * NQc + n;
            L   += w * d_Pl[base];
            val += w * d_Pacc[base * DA + a];
        }
        res += d_gate[(size_t)h * NQc + n] * val / L;
    }
    d_comb[(size_t)n * DA + a] = res;
}

// ---------------- output projection: out = comb @ Wo + bo ---------------------------
// grid (NQ, 4), block 64; o = blockIdx.y*64 + tid
__global__ void outproj_kernel(const float* __restrict__ Wo, const float* __restrict__ bo,
                               float* __restrict__ out) {
    const int n = blockIdx.x;
    const int o = blockIdx.y * 64 + threadIdx.x;
    float acc = bo[o];
    const float* c = &d_comb[(size_t)n * DA];
#pragma unroll
    for (int a = 0; a < DA; a++) acc += c[a] * Wo[(size_t)a * DOUTc + o];
    out[(size_t)n * DOUTc + o] = acc;
}

// ---------------- launch -------------------------------------------------------------
extern "C" void kernel_launch(void* const* d_in, const int* in_sizes, int n_in,
                              void* d_out, int out_size) {
    const float* xQ   = (const float*)d_in[0];
    const float* xK   = (const float*)d_in[1];
    const int*   mask = (const int*)d_in[2];
    const float* Wq   = (const float*)d_in[3];
    const float* Wk   = (const float*)d_in[4];
    const float* Wv   = (const float*)d_in[5];
    const float* Wg   = (const float*)d_in[6];
    const float* bg   = (const float*)d_in[7];
    const float* Wo   = (const float*)d_in[8];
    const float* bo   = (const float*)d_in[9];
    float* out = (float*)d_out;

    proj_kernel<<<dim3(NQc / 32, Hc), 256>>>(xQ, Wq, 0, NQc);
    proj_kernel<<<dim3(NKc / 32, Hc), 256>>>(xK, Wk, 1, NKc);
    proj_kernel<<<dim3(NKc / 32, Hc), 256>>>(xK, Wv, 2, NKc);
    gate_kernel<<<(Hc * NQc * 32) / 256, 256>>>(xQ, Wg, bg);
    attn_kernel<<<dim3(NQc / 32, SSPLIT), 128>>>(mask);
    combine_kernel<<<NQc, 64>>>();
    outproj_kernel<<<dim3(NQc, DOUTc / 64), 64>>>(Wo, bo, out);
}

// round 3
// speedup vs baseline: 4.9339x; 4.9339x over previous
#include <cuda_runtime.h>
#include <math.h>
#include <math_constants.h>

// Problem constants
#define NQc   4096
#define NKc   8192
#define DIN   256
#define DA    64
#define Hc    4
#define DOUTc 256
#define SPLIT 4
#define KCH   (NKc / SPLIT)     // 2048 keys per split
#define KT    64                // keys per smem tile
#define BQ    128               // queries per attn block (8 warps x 16)
#define NEGINF (-CUDART_INF_F)

// ---------------- scratch (static device arrays; no cudaMalloc) ----------------
__device__ float    d_Qp[(size_t)Hc * NQc * DA];              // 4 MB  (pre-scaled by 1/8)
__device__ float    d_Kp[(size_t)Hc * NKc * DA];              // 8 MB
__device__ float    d_Vp[(size_t)Hc * NKc * DA];              // 8 MB
__device__ float    d_gate[(size_t)Hc * NQc];
__device__ float    d_Pacc[(size_t)Hc * SPLIT * NQc * DA];    // 16 MB
__device__ float    d_Pm[(size_t)Hc * SPLIT * NQc];
__device__ float    d_Pl[(size_t)Hc * SPLIT * NQc];
__device__ float    d_comb[(size_t)NQc * DA];
__device__ unsigned d_mbits[(size_t)NQc * (NKc / 32)];        // 4 MB bitmask

// ---------------- helpers -------------------------------------------------------
__device__ __forceinline__ unsigned f2tf(float x) {
    unsigned u;
    asm("cvt.rna.tf32.f32 %0, %1;" : "=r"(u) : "f"(x));
    return u;
}
__device__ __forceinline__ float f2tf_f(float x) { return __uint_as_float(f2tf(x)); }

__device__ __forceinline__ void mma_tf32(float c[4], const unsigned a[4],
                                         unsigned b0, unsigned b1) {
    asm volatile(
        "mma.sync.aligned.m16n8k8.row.col.f32.tf32.tf32.f32 "
        "{%0,%1,%2,%3}, {%4,%5,%6,%7}, {%8,%9}, {%0,%1,%2,%3};"
        : "+f"(c[0]), "+f"(c[1]), "+f"(c[2]), "+f"(c[3])
        : "r"(a[0]), "r"(a[1]), "r"(a[2]), "r"(a[3]), "r"(b0), "r"(b1));
}

// ---------------- mask bit-pack: 134MB int32 -> 4MB bits ------------------------
// warp handles 1024 consecutive mask ints -> 32 words (bit i of word w <-> int w*32+i)
__global__ void maskpack_kernel(const int* __restrict__ mask) {
    int t = blockIdx.x * blockDim.x + threadIdx.x;
    int w = t >> 5, lane = t & 31;
    size_t base = (size_t)w * 1024;
    unsigned mine = 0;
#pragma unroll
    for (int i = 0; i < 32; i++) {
        int v = mask[base + (size_t)i * 32 + lane];
        unsigned bal = __ballot_sync(0xffffffffu, v != 0);
        if (lane == i) mine = bal;
    }
    d_mbits[(size_t)w * 32 + lane] = mine;
}

// ---------------- tf32 mma projection: out[h][n][a] = sum_k x[n][k] W[h][k][a] --
// block = 128 thr (4 warps x 16 rows), tile 64n x 64a, loop k in 4 chunks of 64
__global__ __launch_bounds__(128) void proj_mma(const float* __restrict__ x,
                                                const float* __restrict__ W,
                                                int which, int N) {
    __shared__ float Xs[64][68];   // stride 68: conflict-free A-frag loads
    __shared__ float Ws[64][72];   // stride 72: conflict-free B-frag loads
    float* outp = (which == 0) ? d_Qp : (which == 1) ? d_Kp : d_Vp;
    const float oscale = (which == 0) ? 0.125f : 1.0f;   // fold 1/sqrt(64) into Q
    const int t = threadIdx.x, w = t >> 5, lane = t & 31;
    const int grp = lane >> 2, qd = lane & 3;
    const int h = blockIdx.y, n0 = blockIdx.x * 64;

    float C[8][4];
#pragma unroll
    for (int j = 0; j < 8; j++)
#pragma unroll
        for (int e = 0; e < 4; e++) C[j][e] = 0.f;

    for (int k0 = 0; k0 < DIN; k0 += 64) {
        // Xs: 64x64 floats -> 8 float4 per thread
#pragma unroll
        for (int it = 0; it < 8; it++) {
            int idx = it * 128 + t;
            int row = idx >> 4, c4 = (idx & 15) * 4;
            float4 v = *(const float4*)&x[(size_t)(n0 + row) * DIN + k0 + c4];
            Xs[row][c4 + 0] = f2tf_f(v.x); Xs[row][c4 + 1] = f2tf_f(v.y);
            Xs[row][c4 + 2] = f2tf_f(v.z); Xs[row][c4 + 3] = f2tf_f(v.w);
        }
        // Ws: 64x64 floats
#pragma unroll
        for (int it = 0; it < 8; it++) {
            int idx = it * 128 + t;
            int row = idx >> 4, c4 = (idx & 15) * 4;
            float4 v = *(const float4*)&W[((size_t)h * DIN + k0 + row) * DA + c4];
            Ws[row][c4 + 0] = f2tf_f(v.x); Ws[row][c4 + 1] = f2tf_f(v.y);
            Ws[row][c4 + 2] = f2tf_f(v.z); Ws[row][c4 + 3] = f2tf_f(v.w);
        }
        __syncthreads();
#pragma unroll
        for (int s = 0; s < 8; s++) {
            unsigned a[4];
            a[0] = __float_as_uint(Xs[w * 16 + grp][s * 8 + qd]);
            a[1] = __float_as_uint(Xs[w * 16 + grp + 8][s * 8 + qd]);
            a[2] = __float_as_uint(Xs[w * 16 + grp][s * 8 + qd + 4]);
            a[3] = __float_as_uint(Xs[w * 16 + grp + 8][s * 8 + qd + 4]);
#pragma unroll
            for (int j = 0; j < 8; j++) {
                unsigned b0 = __float_as_uint(Ws[s * 8 + qd][j * 8 + grp]);
                unsigned b1 = __float_as_uint(Ws[s * 8 + qd + 4][j * 8 + grp]);
                mma_tf32(C[j], a, b0, b1);
            }
        }
        __syncthreads();
    }
    int row = n0 + w * 16 + grp;
    float* olo = outp + ((size_t)h * N + row) * DA;
    float* ohi = outp + ((size_t)h * N + row + 8) * DA;
#pragma unroll
    for (int j = 0; j < 8; j++) {
        *(float2*)&olo[j * 8 + 2 * qd] = make_float2(C[j][0] * oscale, C[j][1] * oscale);
        *(float2*)&ohi[j * 8 + 2 * qd] = make_float2(C[j][2] * oscale, C[j][3] * oscale);
    }
}

// ---------------- gates ---------------------------------------------------------
__global__ void gate_kernel(const float* __restrict__ xQ, const float* __restrict__ Wg,
                            const float* __restrict__ bg) {
    int gid  = blockIdx.x * blockDim.x + threadIdx.x;
    int w    = gid >> 5;
    int lane = gid & 31;
    if (w >= Hc * NQc) return;
    int h = w >> 12;
    int n = w & (NQc - 1);
    const float4* xp = (const float4*)(xQ + (size_t)n * DIN);
    const float4* wp = (const float4*)(Wg + (size_t)h * DIN);
    float acc = 0.f;
#pragma unroll
    for (int i = 0; i < 2; i++) {
        float4 xa = xp[lane + 32 * i], wa = wp[lane + 32 * i];
        acc += xa.x * wa.x + xa.y * wa.y + xa.z * wa.z + xa.w * wa.w;
    }
#pragma unroll
    for (int off = 16; off; off >>= 1) acc += __shfl_xor_sync(0xffffffffu, acc, off);
    if (lane == 0) d_gate[w] = 1.f / (1.f + __expf(-(acc + bg[h])));
}

// ---------------- tensor-core flash attention -----------------------------------
// grid (NQ/128, H, SPLIT); 256 thr = 8 warps, warp w -> 16 queries
__global__ __launch_bounds__(256) void attn_mma_kernel() {
    __shared__ float Ks[KT][68];          // stride 68: B-frag loads conflict-free
    __shared__ float Vs[KT][72];          // stride 72: B-frag loads conflict-free
    __shared__ unsigned bs[BQ][2];        // 64 mask bits per query row per ktile

    const int t = threadIdx.x, w = t >> 5, lane = t & 31;
    const int grp = lane >> 2, qd = lane & 3;
    const int h = blockIdx.y, sp = blockIdx.z;
    const int q0 = blockIdx.x * BQ;
    const int qrow = q0 + w * 16;

    // Q fragments (tf32), resident in registers; scale already folded in
    unsigned Qf[8][4];
    {
        const float* Qb = d_Qp + ((size_t)h * NQc + qrow) * DA;
#pragma unroll
        for (int s = 0; s < 8; s++) {
            Qf[s][0] = f2tf(Qb[(size_t)grp * DA + s * 8 + qd]);
            Qf[s][1] = f2tf(Qb[(size_t)(grp + 8) * DA + s * 8 + qd]);
            Qf[s][2] = f2tf(Qb[(size_t)grp * DA + s * 8 + qd + 4]);
            Qf[s][3] = f2tf(Qb[(size_t)(grp + 8) * DA + s * 8 + qd + 4]);
        }
    }

    float O[8][4];
#pragma unroll
    for (int j = 0; j < 8; j++)
#pragma unroll
        for (int e = 0; e < 4; e++) O[j][e] = 0.f;
    float mlo = NEGINF, mhi = NEGINF, llo = 0.f, lhi = 0.f;

    const int tq   = qd >> 1;
    const int par  = qd & 1;
    const int src0 = (lane & ~3) | tq;
    const int src1 = src0 + 2;

    for (int tile = 0; tile < KCH / KT; tile++) {
        const int kb = sp * KCH + tile * KT;
        // load K/V tiles (cvt to tf32 at store) — 4 float4 per thread each
#pragma unroll
        for (int it = 0; it < 4; it++) {
            int idx = it * 256 + t;
            int row = idx >> 4, c4 = (idx & 15) * 4;
            float4 kv = *(const float4*)&d_Kp[((size_t)h * NKc + kb + row) * DA + c4];
            Ks[row][c4 + 0] = f2tf_f(kv.x); Ks[row][c4 + 1] = f2tf_f(kv.y);
            Ks[row][c4 + 2] = f2tf_f(kv.z); Ks[row][c4 + 3] = f2tf_f(kv.w);
            float4 vv = *(const float4*)&d_Vp[((size_t)h * NKc + kb + row) * DA + c4];
            Vs[row][c4 + 0] = f2tf_f(vv.x); Vs[row][c4 + 1] = f2tf_f(vv.y);
            Vs[row][c4 + 2] = f2tf_f(vv.z); Vs[row][c4 + 3] = f2tf_f(vv.w);
        }
        // mask bits: row t>>1, word t&1
        bs[t >> 1][t & 1] = d_mbits[(size_t)(q0 + (t >> 1)) * (NKc / 32) + (kb >> 5) + (t & 1)];
        __syncthreads();

        // ---- scores S = Q K^T ----
        float S[8][4];
#pragma unroll
        for (int j = 0; j < 8; j++)
#pragma unroll
            for (int e = 0; e < 4; e++) S[j][e] = 0.f;
#pragma unroll
        for (int s = 0; s < 8; s++) {
#pragma unroll
            for (int j = 0; j < 8; j++) {
                unsigned b0 = __float_as_uint(Ks[j * 8 + grp][s * 8 + qd]);
                unsigned b1 = __float_as_uint(Ks[j * 8 + grp][s * 8 + qd + 4]);
                mma_tf32(S[j], Qf[s], b0, b1);
            }
        }

        // ---- mask + row max ----
        unsigned wl0 = bs[w * 16 + grp][0],     wl1 = bs[w * 16 + grp][1];
        unsigned wh0 = bs[w * 16 + grp + 8][0], wh1 = bs[w * 16 + grp + 8][1];
        float tlo = NEGINF, thi = NEGINF;
#pragma unroll
        for (int j = 0; j < 8; j++) {
            int c = j * 8 + 2 * qd;   // even, c and c+1 in same word
            unsigned lo = (c < 32) ? (wl0 >> c) : (wl1 >> (c - 32));
            unsigned hi = (c < 32) ? (wh0 >> c) : (wh1 >> (c - 32));
            if (!(lo & 1u)) S[j][0] = NEGINF;
            if (!(lo & 2u)) S[j][1] = NEGINF;
            if (!(hi & 1u)) S[j][2] = NEGINF;
            if (!(hi & 2u)) S[j][3] = NEGINF;
            tlo = fmaxf(tlo, fmaxf(S[j][0], S[j][1]));
            thi = fmaxf(thi, fmaxf(S[j][2], S[j][3]));
        }
        tlo = fmaxf(tlo, __shfl_xor_sync(0xffffffffu, tlo, 1));
        tlo = fmaxf(tlo, __shfl_xor_sync(0xffffffffu, tlo, 2));
        thi = fmaxf(thi, __shfl_xor_sync(0xffffffffu, thi, 1));
        thi = fmaxf(thi, __shfl_xor_sync(0xffffffffu, thi, 2));

        float nmlo = fmaxf(mlo, tlo), nmhi = fmaxf(mhi, thi);
        float smlo = (nmlo > NEGINF) ? nmlo : 0.f;
        float smhi = (nmhi > NEGINF) ? nmhi : 0.f;
        float clo = __expf(mlo - smlo), chi = __expf(mhi - smhi);

        // ---- exp + row sum ----
        float pslo = 0.f, pshi = 0.f;
#pragma unroll
        for (int j = 0; j < 8; j++) {
            S[j][0] = __expf(S[j][0] - smlo);
            S[j][1] = __expf(S[j][1] - smlo);
            S[j][2] = __expf(S[j][2] - smhi);
            S[j][3] = __expf(S[j][3] - smhi);
            pslo += S[j][0] + S[j][1];
            pshi += S[j][2] + S[j][3];
        }
        pslo += __shfl_xor_sync(0xffffffffu, pslo, 1);
        pslo += __shfl_xor_sync(0xffffffffu, pslo, 2);
        pshi += __shfl_xor_sync(0xffffffffu, pshi, 1);
        pshi += __shfl_xor_sync(0xffffffffu, pshi, 2);
        llo = llo * clo + pslo;
        lhi = lhi * chi + pshi;

        // ---- rescale O ----
#pragma unroll
        for (int j = 0; j < 8; j++) {
            O[j][0] *= clo; O[j][1] *= clo;
            O[j][2] *= chi; O[j][3] *= chi;
        }
        mlo = nmlo; mhi = nmhi;

        // ---- O += P V : C-frag -> A-frag via intra-quad shuffles ----
#pragma unroll
        for (int s = 0; s < 8; s++) {
            float x00 = __shfl_sync(0xffffffffu, S[s][0], src0);
            float x01 = __shfl_sync(0xffffffffu, S[s][1], src0);
            float x10 = __shfl_sync(0xffffffffu, S[s][0], src1);
            float x11 = __shfl_sync(0xffffffffu, S[s][1], src1);
            float y00 = __shfl_sync(0xffffffffu, S[s][2], src0);
            float y01 = __shfl_sync(0xffffffffu, S[s][3], src0);
            float y10 = __shfl_sync(0xffffffffu, S[s][2], src1);
            float y11 = __shfl_sync(0xffffffffu, S[s][3], src1);
            unsigned A[4];
            A[0] = f2tf(par ? x01 : x00);
            A[1] = f2tf(par ? y01 : y00);
            A[2] = f2tf(par ? x11 : x10);
            A[3] = f2tf(par ? y11 : y10);
#pragma unroll
            for (int j = 0; j < 8; j++) {
                unsigned b0 = __float_as_uint(Vs[s * 8 + qd][j * 8 + grp]);
                unsigned b1 = __float_as_uint(Vs[s * 8 + qd + 4][j * 8 + grp]);
                mma_tf32(O[j], A, b0, b1);
            }
        }
        __syncthreads();
    }

    // ---- store partials ----
    size_t pbase = ((size_t)h * SPLIT + sp) * NQc + qrow;
    if (qd == 0) {
        d_Pm[pbase + grp]     = mlo;
        d_Pm[pbase + grp + 8] = mhi;
        d_Pl[pbase + grp]     = llo;
        d_Pl[pbase + grp + 8] = lhi;
    }
    float* oblo = d_Pacc + (pbase + grp) * DA;
    float* obhi = d_Pacc + (pbase + grp + 8) * DA;
#pragma unroll
    for (int j = 0; j < 8; j++) {
        *(float2*)&oblo[j * 8 + 2 * qd] = make_float2(O[j][0], O[j][1]);
        *(float2*)&obhi[j * 8 + 2 * qd] = make_float2(O[j][2], O[j][3]);
    }
}

// ---------------- merge splits + gate combine ------------------------------------
__global__ void combine_kernel() {
    const int n = blockIdx.x;
    const int a = threadIdx.x;
    float res = 0.f;
#pragma unroll
    for (int h = 0; h < Hc; h++) {
        float mv[SPLIT];
        float M = NEGINF;
#pragma unroll
        for (int s = 0; s < SPLIT; s++) {
            mv[s] = d_Pm[((size_t)h * SPLIT + s) * NQc + n];
            M = fmaxf(M, mv[s]);
        }
        if (!(M > NEGINF)) continue;
        float L = 0.f, val = 0.f;
#pragma unroll
        for (int s = 0; s < SPLIT; s++) {
            float wgt = __expf(mv[s] - M);
            size_t base = ((size_t)h * SPLIT + s) * NQc + n;
            L   += wgt * d_Pl[base];
            val += wgt * d_Pacc[base * DA + a];
        }
        res += d_gate[(size_t)h * NQc + n] * val / L;
    }
    d_comb[(size_t)n * DA + a] = res;
}

// ---------------- output projection ----------------------------------------------
__global__ void outproj_kernel(const float* __restrict__ Wo, const float* __restrict__ bo,
                               float* __restrict__ out) {
    const int n = blockIdx.x;
    const int o = blockIdx.y * 64 + threadIdx.x;
    float acc = bo[o];
    const float* c = &d_comb[(size_t)n * DA];
#pragma unroll
    for (int a = 0; a < DA; a++) acc += c[a] * Wo[(size_t)a * DOUTc + o];
    out[(size_t)n * DOUTc + o] = acc;
}

// ---------------- launch ----------------------------------------------------------
extern "C" void kernel_launch(void* const* d_in, const int* in_sizes, int n_in,
                              void* d_out, int out_size) {
    const float* xQ   = (const float*)d_in[0];
    const float* xK   = (const float*)d_in[1];
    const int*   mask = (const int*)d_in[2];
    const float* Wq   = (const float*)d_in[3];
    const float* Wk   = (const float*)d_in[4];
    const float* Wv   = (const float*)d_in[5];
    const float* Wg   = (const float*)d_in[6];
    const float* bg   = (const float*)d_in[7];
    const float* Wo   = (const float*)d_in[8];
    const float* bo   = (const float*)d_in[9];
    float* out = (float*)d_out;

    maskpack_kernel<<<(NQc * (NKc / 1024)) * 32 / 256, 256>>>(mask);
    proj_mma<<<dim3(NQc / 64, Hc), 128>>>(xQ, Wq, 0, NQc);
    proj_mma<<<dim3(NKc / 64, Hc), 128>>>(xK, Wk, 1, NKc);
    proj_mma<<<dim3(NKc / 64, Hc), 128>>>(xK, Wv, 2, NKc);
    gate_kernel<<<(Hc * NQc * 32) / 256, 256>>>(xQ, Wg, bg);
    attn_mma_kernel<<<dim3(NQc / BQ, Hc, SPLIT), 256>>>();
    combine_kernel<<<NQc, DA>>>();
    outproj_kernel<<<dim3(NQc, DOUTc / 64), 64>>>(Wo, bo, out);
}

// round 5
// speedup vs baseline: 8.7808x; 1.7797x over previous
#include <cuda_runtime.h>
#include <cuda_bf16.h>
#include <math.h>
#include <math_constants.h>

#define NQc   4096
#define NKc   8192
#define DIN   256
#define DA    64
#define Hc    4
#define DOUTc 256
#define SPLIT 4
#define KCH   (NKc / SPLIT)     // 2048 keys per split
#define KT    64                // keys per tile
#define BQ    128               // queries per attn block
#define NEGINF (-CUDART_INF_F)
#define QSCALE (0.125f * 1.4426950408889634f)   // 1/sqrt(64) * log2(e), folded into Wq

typedef __nv_bfloat16 bf16;

// ---------------- scratch (static device arrays; no runtime API needed) ----------
__device__ bf16     d_xQb[(size_t)NQc * DIN];
__device__ bf16     d_xKb[(size_t)NKc * DIN];
__device__ bf16     d_Wqt[(size_t)Hc * DA * DIN];   // [h][a][k]
__device__ bf16     d_Wkt[(size_t)Hc * DA * DIN];
__device__ bf16     d_Wvt[(size_t)Hc * DA * DIN];
__device__ bf16     d_Qp[(size_t)Hc * NQc * DA];    // [h][n][a]  (log2-scaled)
__device__ bf16     d_Kp[(size_t)Hc * NKc * DA];    // [h][n][a]
__device__ bf16     d_Vt[(size_t)Hc * DA * NKc];    // [h][a][n]  transposed
__device__ float    d_gate[(size_t)Hc * NQc];
__device__ float    d_Pacc[(size_t)Hc * SPLIT * NQc * DA];
__device__ float    d_Pm[(size_t)Hc * SPLIT * NQc];
__device__ float    d_Pl[(size_t)Hc * SPLIT * NQc];
__device__ float    d_comb[(size_t)NQc * DA];
__device__ unsigned d_mbits[(size_t)NQc * (NKc / 32)];

// ---------------- helpers ----------------
__device__ __forceinline__ float ex2(float x) {
    float y;
    asm("ex2.approx.f32 %0, %1;" : "=f"(y) : "f"(x));
    return y;   // ex2(-inf) = 0
}
__device__ __forceinline__ unsigned packbf(float lo, float hi) {
    __nv_bfloat162 p = __float22bfloat162_rn(make_float2(lo, hi));
    return *(unsigned*)&p;
}
__device__ __forceinline__ void mma_bf16(float c[4], unsigned a0, unsigned a1,
                                         unsigned a2, unsigned a3,
                                         unsigned b0, unsigned b1) {
    asm volatile(
        "mma.sync.aligned.m16n8k16.row.col.f32.bf16.bf16.f32 "
        "{%0,%1,%2,%3}, {%4,%5,%6,%7}, {%8,%9}, {%0,%1,%2,%3};"
        : "+f"(c[0]), "+f"(c[1]), "+f"(c[2]), "+f"(c[3])
        : "r"(a0), "r"(a1), "r"(a2), "r"(a3), "r"(b0), "r"(b1));
}
__device__ __forceinline__ void cp16(void* dst, const void* src) {
    unsigned d = (unsigned)__cvta_generic_to_shared(dst);
    asm volatile("cp.async.cg.shared.global [%0], [%1], 16;" :: "r"(d), "l"(src));
}
__device__ __forceinline__ void cp8(void* dst, const void* src) {
    unsigned d = (unsigned)__cvta_generic_to_shared(dst);
    asm volatile("cp.async.ca.shared.global [%0], [%1], 8;" :: "r"(d), "l"(src));
}
#define CP_COMMIT() asm volatile("cp.async.commit_group;")
#define CP_WAIT(n)  asm volatile("cp.async.wait_group %0;" :: "n"(n))

// ---------------- prep: fp32 -> bf16 (writes device globals directly) -----------
__global__ void cvt_bf16_kernel(const float* __restrict__ src, int which) {
    bf16* dst = (which == 0) ? d_xQb : d_xKb;
    size_t i = ((size_t)blockIdx.x * blockDim.x + threadIdx.x) * 4;
    float4 v = *(const float4*)(src + i);
    uint2 o;
    o.x = packbf(v.x, v.y);
    o.y = packbf(v.z, v.w);
    *(uint2*)(dst + i) = o;
}

// Wt[h][a][k] = W[h][k][a] * scale
__global__ void prep_w_kernel(const float* __restrict__ W, int which, float scale) {
    bf16* Wt = (which == 0) ? d_Wqt : (which == 1) ? d_Wkt : d_Wvt;
    int h = blockIdx.y;
    int idx = blockIdx.x * blockDim.x + threadIdx.x;   // a*256+k
    int a = idx >> 8, k = idx & 255;
    Wt[((size_t)h * DA + a) * DIN + k] =
        __float2bfloat16_rn(W[((size_t)h * DIN + k) * DA + a] * scale);
}

// ---------------- mask bit-pack: 134MB int32 -> 4MB bits --------------------------
__global__ void maskpack_kernel(const int* __restrict__ mask) {
    int t = blockIdx.x * blockDim.x + threadIdx.x;
    int w = t >> 5, lane = t & 31;
    size_t base = (size_t)w * 1024;
    unsigned mine = 0;
#pragma unroll
    for (int i = 0; i < 32; i++) {
        int v = mask[base + (size_t)i * 32 + lane];
        unsigned bal = __ballot_sync(0xffffffffu, v != 0);
        if (lane == i) mine = bal;
    }
    d_mbits[(size_t)w * 32 + lane] = mine;
}

// ---------------- bf16 projection: out[n][a] = sum_k X[n][k] * Wt[a][k] -----------
// block 256 (8 warps), tile 128n x 64a, k in 4 chunks of 64
__global__ __launch_bounds__(256) void proj_bf(int which, int N) {
    __shared__ __align__(16) bf16 Xs[128][72];   // 144B rows: frag loads conflict-free
    __shared__ __align__(16) bf16 Ws[64][72];
    const bf16* X  = (which == 0) ? d_xQb : d_xKb;
    const bf16* Wt = (which == 0) ? d_Wqt : (which == 1) ? d_Wkt : d_Wvt;
    const int t = threadIdx.x, w = t >> 5, lane = t & 31;
    const int grp = lane >> 2, qd = lane & 3;
    const int h = blockIdx.y, n0 = blockIdx.x * 128;

    float C[8][4];
#pragma unroll
    for (int j = 0; j < 8; j++)
#pragma unroll
        for (int e = 0; e < 4; e++) C[j][e] = 0.f;

    for (int k0 = 0; k0 < DIN; k0 += 64) {
#pragma unroll
        for (int it = 0; it < 4; it++) {
            int idx = it * 256 + t;
            int row = idx >> 3, c = idx & 7;
            cp16(&Xs[row][c * 8], &X[(size_t)(n0 + row) * DIN + k0 + c * 8]);
        }
#pragma unroll
        for (int it = 0; it < 2; it++) {
            int idx = it * 256 + t;
            int row = idx >> 3, c = idx & 7;
            cp16(&Ws[row][c * 8], &Wt[((size_t)h * DA + row) * DIN + k0 + c * 8]);
        }
        CP_COMMIT();
        CP_WAIT(0);
        __syncthreads();
#pragma unroll
        for (int s = 0; s < 4; s++) {
            unsigned a0 = *(unsigned*)&Xs[w * 16 + grp][s * 16 + 2 * qd];
            unsigned a1 = *(unsigned*)&Xs[w * 16 + grp + 8][s * 16 + 2 * qd];
            unsigned a2 = *(unsigned*)&Xs[w * 16 + grp][s * 16 + 2 * qd + 8];
            unsigned a3 = *(unsigned*)&Xs[w * 16 + grp + 8][s * 16 + 2 * qd + 8];
#pragma unroll
            for (int j = 0; j < 8; j++) {
                unsigned b0 = *(unsigned*)&Ws[j * 8 + grp][s * 16 + 2 * qd];
                unsigned b1 = *(unsigned*)&Ws[j * 8 + grp][s * 16 + 2 * qd + 8];
                mma_bf16(C[j], a0, a1, a2, a3, b0, b1);
            }
        }
        __syncthreads();
    }

    const int nlo = n0 + w * 16 + grp, nhi = nlo + 8;
    if (which == 2) {
        // V: store transposed d_Vt[h][a][n]
#pragma unroll
        for (int j = 0; j < 8; j++) {
            int a = j * 8 + 2 * qd;
            d_Vt[((size_t)h * DA + a) * NKc + nlo]     = __float2bfloat16_rn(C[j][0]);
            d_Vt[((size_t)h * DA + a + 1) * NKc + nlo] = __float2bfloat16_rn(C[j][1]);
            d_Vt[((size_t)h * DA + a) * NKc + nhi]     = __float2bfloat16_rn(C[j][2]);
            d_Vt[((size_t)h * DA + a + 1) * NKc + nhi] = __float2bfloat16_rn(C[j][3]);
        }
    } else {
        bf16* outp = (which == 0) ? d_Qp : d_Kp;
        bf16* olo = outp + ((size_t)h * N + nlo) * DA;
        bf16* ohi = outp + ((size_t)h * N + nhi) * DA;
#pragma unroll
        for (int j = 0; j < 8; j++) {
            *(unsigned*)&olo[j * 8 + 2 * qd] = packbf(C[j][0], C[j][1]);
            *(unsigned*)&ohi[j * 8 + 2 * qd] = packbf(C[j][2], C[j][3]);
        }
    }
}

// ---------------- gates ----------------
__global__ void gate_kernel(const float* __restrict__ xQ, const float* __restrict__ Wg,
                            const float* __restrict__ bg) {
    int gid  = blockIdx.x * blockDim.x + threadIdx.x;
    int w    = gid >> 5;
    int lane = gid & 31;
    if (w >= Hc * NQc) return;
    int h = w >> 12;
    int n = w & (NQc - 1);
    const float4* xp = (const float4*)(xQ + (size_t)n * DIN);
    const float4* wp = (const float4*)(Wg + (size_t)h * DIN);
    float acc = 0.f;
#pragma unroll
    for (int i = 0; i < 2; i++) {
        float4 xa = xp[lane + 32 * i], wa = wp[lane + 32 * i];
        acc += xa.x * wa.x + xa.y * wa.y + xa.z * wa.z + xa.w * wa.w;
    }
#pragma unroll
    for (int off = 16; off; off >>= 1) acc += __shfl_xor_sync(0xffffffffu, acc, off);
    if (lane == 0) d_gate[w] = 1.f / (1.f + __expf(-(acc + bg[h])));
}

// ---------------- bf16 flash attention, double-buffered cp.async ------------------
// grid (NQ/128, H, SPLIT); 256 thr = 8 warps x 16 queries
__global__ __launch_bounds__(256) void attn_bf16_kernel() {
    __shared__ __align__(16) bf16 Ks[2][KT][72];   // [key][d]
    __shared__ __align__(16) bf16 Vs[2][DA][72];   // [d][key] (transposed)
    __shared__ __align__(16) unsigned bs[2][BQ][2];

    const int t = threadIdx.x, w = t >> 5, lane = t & 31;
    const int grp = lane >> 2, qd = lane & 3;
    const int h = blockIdx.y, sp = blockIdx.z;
    const int q0 = blockIdx.x * BQ;
    const int qrow = q0 + w * 16;

    // Q fragments (bf16x2), 4 k-steps x 4 regs
    unsigned Qf[4][4];
    {
        const bf16* Qb = d_Qp + ((size_t)h * NQc + qrow) * DA;
#pragma unroll
        for (int s = 0; s < 4; s++) {
            Qf[s][0] = *(const unsigned*)&Qb[(size_t)grp * DA + s * 16 + 2 * qd];
            Qf[s][1] = *(const unsigned*)&Qb[(size_t)(grp + 8) * DA + s * 16 + 2 * qd];
            Qf[s][2] = *(const unsigned*)&Qb[(size_t)grp * DA + s * 16 + 2 * qd + 8];
            Qf[s][3] = *(const unsigned*)&Qb[(size_t)(grp + 8) * DA + s * 16 + 2 * qd + 8];
        }
    }

    float O[8][4];
#pragma unroll
    for (int j = 0; j < 8; j++)
#pragma unroll
        for (int e = 0; e < 4; e++) O[j][e] = 0.f;
    float mlo = NEGINF, mhi = NEGINF, llo = 0.f, lhi = 0.f;

    const int kbase = sp * KCH;
    const int NT = KCH / KT;   // 32 tiles

    auto load_tile = [&](int st, int tile) {
        int kb = kbase + tile * KT;
#pragma unroll
        for (int it = 0; it < 2; it++) {
            int idx = it * 256 + t;
            int row = idx >> 3, c = idx & 7;
            cp16(&Ks[st][row][c * 8], &d_Kp[((size_t)h * NKc + kb + row) * DA + c * 8]);
            cp16(&Vs[st][row][c * 8], &d_Vt[((size_t)h * DA + row) * NKc + kb + c * 8]);
        }
        if (t < BQ)
            cp8(&bs[st][t][0], &d_mbits[(size_t)(q0 + t) * (NKc / 32) + (kb >> 5)]);
        CP_COMMIT();
    };

    load_tile(0, 0);
    load_tile(1, 1);

    for (int tile = 0; tile < NT; tile++) {
        const int st = tile & 1;
        CP_WAIT(1);
        __syncthreads();

        // ---- S = Q K^T (log2-scaled) ----
        float S[8][4];
#pragma unroll
        for (int j = 0; j < 8; j++)
#pragma unroll
            for (int e = 0; e < 4; e++) S[j][e] = 0.f;
#pragma unroll
        for (int s = 0; s < 4; s++) {
#pragma unroll
            for (int j = 0; j < 8; j++) {
                unsigned b0 = *(unsigned*)&Ks[st][j * 8 + grp][s * 16 + 2 * qd];
                unsigned b1 = *(unsigned*)&Ks[st][j * 8 + grp][s * 16 + 2 * qd + 8];
                mma_bf16(S[j], Qf[s][0], Qf[s][1], Qf[s][2], Qf[s][3], b0, b1);
            }
        }

        // ---- mask + row max ----
        unsigned wl0 = bs[st][w * 16 + grp][0],     wl1 = bs[st][w * 16 + grp][1];
        unsigned wh0 = bs[st][w * 16 + grp + 8][0], wh1 = bs[st][w * 16 + grp + 8][1];
        float tlo = NEGINF, thi = NEGINF;
#pragma unroll
        for (int j = 0; j < 8; j++) {
            int c = j * 8 + 2 * qd;
            unsigned lo = (c < 32) ? (wl0 >> c) : (wl1 >> (c - 32));
            unsigned hi = (c < 32) ? (wh0 >> c) : (wh1 >> (c - 32));
            if (!(lo & 1u)) S[j][0] = NEGINF;
            if (!(lo & 2u)) S[j][1] = NEGINF;
            if (!(hi & 1u)) S[j][2] = NEGINF;
            if (!(hi & 2u)) S[j][3] = NEGINF;
            tlo = fmaxf(tlo, fmaxf(S[j][0], S[j][1]));
            thi = fmaxf(thi, fmaxf(S[j][2], S[j][3]));
        }
        tlo = fmaxf(tlo, __shfl_xor_sync(0xffffffffu, tlo, 1));
        tlo = fmaxf(tlo, __shfl_xor_sync(0xffffffffu, tlo, 2));
        thi = fmaxf(thi, __shfl_xor_sync(0xffffffffu, thi, 1));
        thi = fmaxf(thi, __shfl_xor_sync(0xffffffffu, thi, 2));

        float nmlo = fmaxf(mlo, tlo), nmhi = fmaxf(mhi, thi);
        float smlo = (nmlo > NEGINF) ? nmlo : 0.f;
        float smhi = (nmhi > NEGINF) ? nmhi : 0.f;
        float clo = ex2(mlo - smlo), chi = ex2(mhi - smhi);

        // ---- p = 2^(s-m), row sums ----
        float pslo = 0.f, pshi = 0.f;
#pragma unroll
        for (int j = 0; j < 8; j++) {
            S[j][0] = ex2(S[j][0] - smlo);
            S[j][1] = ex2(S[j][1] - smlo);
            S[j][2] = ex2(S[j][2] - smhi);
            S[j][3] = ex2(S[j][3] - smhi);
            pslo += S[j][0] + S[j][1];
            pshi += S[j][2] + S[j][3];
        }
        pslo += __shfl_xor_sync(0xffffffffu, pslo, 1);
        pslo += __shfl_xor_sync(0xffffffffu, pslo, 2);
        pshi += __shfl_xor_sync(0xffffffffu, pshi, 1);
        pshi += __shfl_xor_sync(0xffffffffu, pshi, 2);
        llo = llo * clo + pslo;
        lhi = lhi * chi + pshi;
#pragma unroll
        for (int j = 0; j < 8; j++) {
            O[j][0] *= clo; O[j][1] *= clo;
            O[j][2] *= chi; O[j][3] *= chi;
        }
        mlo = nmlo; mhi = nmhi;

        // ---- O += P V : C-frag -> A-frag on same thread (no shuffles) ----
#pragma unroll
        for (int s = 0; s < 4; s++) {
            unsigned A0 = packbf(S[2 * s][0], S[2 * s][1]);
            unsigned A1 = packbf(S[2 * s][2], S[2 * s][3]);
            unsigned A2 = packbf(S[2 * s + 1][0], S[2 * s + 1][1]);
            unsigned A3 = packbf(S[2 * s + 1][2], S[2 * s + 1][3]);
#pragma unroll
            for (int j = 0; j < 8; j++) {
                unsigned b0 = *(unsigned*)&Vs[st][j * 8 + grp][s * 16 + 2 * qd];
                unsigned b1 = *(unsigned*)&Vs[st][j * 8 + grp][s * 16 + 2 * qd + 8];
                mma_bf16(O[j], A0, A1, A2, A3, b0, b1);
            }
        }
        __syncthreads();
        if (tile + 2 < NT) load_tile(st, tile + 2);
        else CP_COMMIT();   // keep group counts aligned for CP_WAIT(1)
    }

    // ---- store partials ----
    size_t pbase = ((size_t)h * SPLIT + sp) * NQc + qrow;
    if (qd == 0) {
        d_Pm[pbase + grp]     = mlo;
        d_Pm[pbase + grp + 8] = mhi;
        d_Pl[pbase + grp]     = llo;
        d_Pl[pbase + grp + 8] = lhi;
    }
    float* oblo = d_Pacc + (pbase + grp) * DA;
    float* obhi = d_Pacc + (pbase + grp + 8) * DA;
#pragma unroll
    for (int j = 0; j < 8; j++) {
        *(float2*)&oblo[j * 8 + 2 * qd] = make_float2(O[j][0], O[j][1]);
        *(float2*)&obhi[j * 8 + 2 * qd] = make_float2(O[j][2], O[j][3]);
    }
}

// ---------------- merge splits + gate combine ------------------------------------
__global__ void combine_kernel() {
    const int n = blockIdx.x;
    const int a = threadIdx.x;
    float res = 0.f;
#pragma unroll
    for (int h = 0; h < Hc; h++) {
        float mv[SPLIT];
        float M = NEGINF;
#pragma unroll
        for (int s = 0; s < SPLIT; s++) {
            mv[s] = d_Pm[((size_t)h * SPLIT + s) * NQc + n];
            M = fmaxf(M, mv[s]);
        }
        if (!(M > NEGINF)) continue;
        float L = 0.f, val = 0.f;
#pragma unroll
        for (int s = 0; s < SPLIT; s++) {
            float wgt = ex2(mv[s] - M);
            size_t base = ((size_t)h * SPLIT + s) * NQc + n;
            L   += wgt * d_Pl[base];
            val += wgt * d_Pacc[base * DA + a];
        }
        res += d_gate[(size_t)h * NQc + n] * val / L;
    }
    d_comb[(size_t)n * DA + a] = res;
}

// ---------------- output projection ----------------------------------------------
__global__ void outproj_kernel(const float* __restrict__ Wo, const float* __restrict__ bo,
                               float* __restrict__ out) {
    const int n = blockIdx.x;
    const int o = blockIdx.y * 64 + threadIdx.x;
    float acc = bo[o];
    const float* c = &d_comb[(size_t)n * DA];
#pragma unroll
    for (int a = 0; a < DA; a++) acc += c[a] * Wo[(size_t)a * DOUTc + o];
    out[(size_t)n * DOUTc + o] = acc;
}

// ---------------- launch ----------------------------------------------------------
extern "C" void kernel_launch(void* const* d_in, const int* in_sizes, int n_in,
                              void* d_out, int out_size) {
    const float* xQ   = (const float*)d_in[0];
    const float* xK   = (const float*)d_in[1];
    const int*   mask = (const int*)d_in[2];
    const float* Wq   = (const float*)d_in[3];
    const float* Wk   = (const float*)d_in[4];
    const float* Wv   = (const float*)d_in[5];
    const float* Wg   = (const float*)d_in[6];
    const float* bg   = (const float*)d_in[7];
    const float* Wo   = (const float*)d_in[8];
    const float* bo   = (const float*)d_in[9];
    float* out = (float*)d_out;

    cvt_bf16_kernel<<<(NQc * DIN) / 1024, 256>>>(xQ, 0);
    cvt_bf16_kernel<<<(NKc * DIN) / 1024, 256>>>(xK, 1);
    prep_w_kernel<<<dim3(64, Hc), 256>>>(Wq, 0, QSCALE);
    prep_w_kernel<<<dim3(64, Hc), 256>>>(Wk, 1, 1.0f);
    prep_w_kernel<<<dim3(64, Hc), 256>>>(Wv, 2, 1.0f);
    maskpack_kernel<<<(NQc * (NKc / 1024)) * 32 / 256, 256>>>(mask);
    gate_kernel<<<(Hc * NQc * 32) / 256, 256>>>(xQ, Wg, bg);
    proj_bf<<<dim3(NQc / 128, Hc), 256>>>(0, NQc);
    proj_bf<<<dim3(NKc / 128, Hc), 256>>>(1, NKc);
    proj_bf<<<dim3(NKc / 128, Hc), 256>>>(2, NKc);
    attn_bf16_kernel<<<dim3(NQc / BQ, Hc, SPLIT), 256>>>();
    combine_kernel<<<NQc, DA>>>();
    outproj_kernel<<<dim3(NQc, DOUTc / 64), 64>>>(Wo, bo, out);
}